// round 14
// baseline (speedup 1.0000x reference)
#include <cuda_runtime.h>
#include <cuda_fp16.h>
#include <cuda_bf16.h>
#include <cstdint>

#define N_NODES 100000
#define HEADS   8
#define UNROLL_S 4   // scatter: deep batching (REDs are fire-and-forget, regs stay low)
#define UNROLL_N 2   // normalize: shallow (gathers + outputs need registers)

// Per-(node, head) sum of exp(e); converted in-place to reciprocals between
// passes. 3.2 MB (L2-resident). Zeroed by memset node.
__device__ float g_sums[N_NODES * HEADS];

__device__ __forceinline__ void exp8(float4& a, float4& b) {
    a.x = __expf(a.x); a.y = __expf(a.y); a.z = __expf(a.z); a.w = __expf(a.w);
    b.x = __expf(b.x); b.y = __expf(b.y); b.z = __expf(b.z); b.w = __expf(b.w);
}

// 256-bit load, L2 evict_last: pin pass-1 e stream in L2 for pass-2 reuse.
__device__ __forceinline__ void ld256_evict_last(const float* p, float4& a, float4& b) {
    uint32_t r0, r1, r2, r3, r4, r5, r6, r7;
    asm volatile("ld.global.L2::evict_last.v8.b32 {%0,%1,%2,%3,%4,%5,%6,%7}, [%8];"
                 : "=r"(r0), "=r"(r1), "=r"(r2), "=r"(r3),
                   "=r"(r4), "=r"(r5), "=r"(r6), "=r"(r7)
                 : "l"(p));
    a.x = __uint_as_float(r0); a.y = __uint_as_float(r1);
    a.z = __uint_as_float(r2); a.w = __uint_as_float(r3);
    b.x = __uint_as_float(r4); b.y = __uint_as_float(r5);
    b.z = __uint_as_float(r6); b.w = __uint_as_float(r7);
}

// 256-bit load, default policy.
__device__ __forceinline__ void ld256(const float* p, float4& a, float4& b) {
    uint32_t r0, r1, r2, r3, r4, r5, r6, r7;
    asm volatile("ld.global.v8.b32 {%0,%1,%2,%3,%4,%5,%6,%7}, [%8];"
                 : "=r"(r0), "=r"(r1), "=r"(r2), "=r"(r3),
                   "=r"(r4), "=r"(r5), "=r"(r6), "=r"(r7)
                 : "l"(p));
    a.x = __uint_as_float(r0); a.y = __uint_as_float(r1);
    a.z = __uint_as_float(r2); a.w = __uint_as_float(r3);
    b.x = __uint_as_float(r4); b.y = __uint_as_float(r5);
    b.z = __uint_as_float(r6); b.w = __uint_as_float(r7);
}

// 256-bit store, L2 evict_first: streaming output must not displace e.
__device__ __forceinline__ void st256_evict_first(float* p, float4 a, float4 b) {
    asm volatile("st.global.L2::evict_first.v8.b32 [%0], {%1,%2,%3,%4,%5,%6,%7,%8};"
                 :: "l"(p),
                    "r"(__float_as_uint(a.x)), "r"(__float_as_uint(a.y)),
                    "r"(__float_as_uint(a.z)), "r"(__float_as_uint(a.w)),
                    "r"(__float_as_uint(b.x)), "r"(__float_as_uint(b.y)),
                    "r"(__float_as_uint(b.z)), "r"(__float_as_uint(b.w))
                 : "memory");
}

// 128-bit vector reductions (HW max width for red.f32).
__device__ __forceinline__ void red_row(float* srow, float4 a, float4 b) {
    asm volatile("red.global.add.v4.f32 [%0], {%1, %2, %3, %4};"
                 :: "l"(srow), "f"(a.x), "f"(a.y), "f"(a.z), "f"(a.w) : "memory");
    asm volatile("red.global.add.v4.f32 [%0], {%1, %2, %3, %4};"
                 :: "l"(srow + 4), "f"(b.x), "f"(b.y), "f"(b.z), "f"(b.w) : "memory");
}

// Pass 1: red-add exp(e) into g_sums[dst]. Warp-strided 4-edge batching, all
// loads front-batched for deep MLP; REDs fire-and-forget.
// dst loads use DEFAULT policy so the 12.8 MB idx array stays in L2 for pass 2.
__global__ __launch_bounds__(256, 6)
void scatter_sum_kernel(const float* __restrict__ e,
                        const int* __restrict__ dst,
                        int E) {
    int base = blockIdx.x * (blockDim.x * UNROLL_S) + threadIdx.x;

    int d[UNROLL_S];
    float4 va[UNROLL_S], vb[UNROLL_S];
#pragma unroll
    for (int k = 0; k < UNROLL_S; k++) {
        int i = base + k * blockDim.x;
        if (i < E) {
            d[k] = dst[i];
            ld256_evict_last(e + (size_t)i * HEADS, va[k], vb[k]);
        }
    }
#pragma unroll
    for (int k = 0; k < UNROLL_S; k++) {
        int i = base + k * blockDim.x;
        if (i < E) {
            float4 a = va[k], b = vb[k];
            exp8(a, b);
            red_row(g_sums + (size_t)d[k] * HEADS, a, b);
        }
    }
}

// Between passes: g_sums[i] = 1 / (g_sums[i] + eps), in place. 800K elements,
// fully L2-resident. Hoists the per-edge divide out of pass 2.
__global__ __launch_bounds__(256)
void recip_kernel(int n4) {
    int i = blockIdx.x * blockDim.x + threadIdx.x;
    if (i >= n4) return;
    const float eps = 1e-16f;
    float4 s = reinterpret_cast<const float4*>(g_sums)[i];
    s.x = __fdividef(1.0f, s.x + eps);
    s.y = __fdividef(1.0f, s.y + eps);
    s.z = __fdividef(1.0f, s.z + eps);
    s.w = __fdividef(1.0f, s.w + eps);
    reinterpret_cast<float4*>(g_sums)[i] = s;
}

// Pass 2: out = exp(e) * rcp[dst]. Pure multiply. Reverse block order so the
// earliest reads hit the L2-resident tail of e left by pass 1.
__global__ __launch_bounds__(256, 6)
void normalize_kernel(const float* __restrict__ e,
                      const int* __restrict__ dst,
                      float* __restrict__ out,
                      int E, int nBlocks) {
    int rb = nBlocks - 1 - blockIdx.x;
    int base = rb * ((int)blockDim.x * UNROLL_N) + threadIdx.x;

    int d[UNROLL_N];
#pragma unroll
    for (int k = 0; k < UNROLL_N; k++) {
        int i = base + k * blockDim.x;
        if (i < E) d[k] = dst[i];
    }

    float4 va[UNROLL_N], vb[UNROLL_N], sa[UNROLL_N], sb[UNROLL_N];
#pragma unroll
    for (int k = 0; k < UNROLL_N; k++) {
        int i = base + k * blockDim.x;
        if (i < E) {
            ld256(e + (size_t)i * HEADS, va[k], vb[k]);         // may hit pinned L2 lines
            ld256(g_sums + (size_t)d[k] * HEADS, sa[k], sb[k]); // L2 gather (reciprocals)
        }
    }

#pragma unroll
    for (int k = 0; k < UNROLL_N; k++) {
        int i = base + k * blockDim.x;
        if (i < E) {
            float4 a = va[k], b = vb[k];
            exp8(a, b);
            float4 s0 = sa[k], s1 = sb[k], o0, o1;
            o0.x = a.x * s0.x; o0.y = a.y * s0.y;
            o0.z = a.z * s0.z; o0.w = a.w * s0.w;
            o1.x = b.x * s1.x; o1.y = b.y * s1.y;
            o1.z = b.z * s1.z; o1.w = b.w * s1.w;
            st256_evict_first(out + (size_t)i * HEADS, o0, o1);
        }
    }
}

extern "C" void kernel_launch(void* const* d_in, const int* in_sizes, int n_in,
                              void* d_out, int out_size) {
    const float* e = (const float*)d_in[0];
    const int* edge_index = (const int*)d_in[1];
    int E = in_sizes[0] / HEADS;
    const int* dst = edge_index + (size_t)E;  // edge_index[1]
    float* out = (float*)d_out;

    // Zero g_sums via a memset graph node.
    void* sums_ptr = nullptr;
    cudaGetSymbolAddress(&sums_ptr, g_sums);
    cudaMemsetAsync(sums_ptr, 0, (size_t)N_NODES * HEADS * sizeof(float));

    const int T = 256;
    int nBlocksS = (E + T * UNROLL_S - 1) / (T * UNROLL_S);
    int nBlocksN = (E + T * UNROLL_N - 1) / (T * UNROLL_N);
    int n4 = N_NODES * HEADS / 4;

    scatter_sum_kernel<<<nBlocksS, T>>>(e, dst, E);
    recip_kernel<<<(n4 + T - 1) / T, T>>>(n4);
    normalize_kernel<<<nBlocksN, T>>>(e, dst, out, E, nBlocksN);
}

// round 15
// speedup vs baseline: 1.0600x; 1.0600x over previous
#include <cuda_runtime.h>
#include <cuda_fp16.h>
#include <cuda_bf16.h>
#include <cstdint>

#define N_NODES 100000
#define HEADS   8
#define UNROLL  2

// Per-(node, head) sum of exp(e); converted in-place to reciprocals between
// passes. 3.2 MB (L2-resident). Zeroed by memset node.
__device__ float g_sums[N_NODES * HEADS];

__device__ __forceinline__ void exp8(float4& a, float4& b) {
    a.x = __expf(a.x); a.y = __expf(a.y); a.z = __expf(a.z); a.w = __expf(a.w);
    b.x = __expf(b.x); b.y = __expf(b.y); b.z = __expf(b.z); b.w = __expf(b.w);
}

// 256-bit load, L2 evict_last: pin pass-1 e stream in L2 for pass-2 reuse.
__device__ __forceinline__ void ld256_evict_last(const float* p, float4& a, float4& b) {
    uint32_t r0, r1, r2, r3, r4, r5, r6, r7;
    asm volatile("ld.global.L2::evict_last.v8.b32 {%0,%1,%2,%3,%4,%5,%6,%7}, [%8];"
                 : "=r"(r0), "=r"(r1), "=r"(r2), "=r"(r3),
                   "=r"(r4), "=r"(r5), "=r"(r6), "=r"(r7)
                 : "l"(p));
    a.x = __uint_as_float(r0); a.y = __uint_as_float(r1);
    a.z = __uint_as_float(r2); a.w = __uint_as_float(r3);
    b.x = __uint_as_float(r4); b.y = __uint_as_float(r5);
    b.z = __uint_as_float(r6); b.w = __uint_as_float(r7);
}

// 256-bit load, default policy.
__device__ __forceinline__ void ld256(const float* p, float4& a, float4& b) {
    uint32_t r0, r1, r2, r3, r4, r5, r6, r7;
    asm volatile("ld.global.v8.b32 {%0,%1,%2,%3,%4,%5,%6,%7}, [%8];"
                 : "=r"(r0), "=r"(r1), "=r"(r2), "=r"(r3),
                   "=r"(r4), "=r"(r5), "=r"(r6), "=r"(r7)
                 : "l"(p));
    a.x = __uint_as_float(r0); a.y = __uint_as_float(r1);
    a.z = __uint_as_float(r2); a.w = __uint_as_float(r3);
    b.x = __uint_as_float(r4); b.y = __uint_as_float(r5);
    b.z = __uint_as_float(r6); b.w = __uint_as_float(r7);
}

// 256-bit store, L2 evict_first: streaming output must not displace e.
__device__ __forceinline__ void st256_evict_first(float* p, float4 a, float4 b) {
    asm volatile("st.global.L2::evict_first.v8.b32 [%0], {%1,%2,%3,%4,%5,%6,%7,%8};"
                 :: "l"(p),
                    "r"(__float_as_uint(a.x)), "r"(__float_as_uint(a.y)),
                    "r"(__float_as_uint(a.z)), "r"(__float_as_uint(a.w)),
                    "r"(__float_as_uint(b.x)), "r"(__float_as_uint(b.y)),
                    "r"(__float_as_uint(b.z)), "r"(__float_as_uint(b.w))
                 : "memory");
}

// 128-bit vector reductions (HW max width for red.f32).
__device__ __forceinline__ void red_row(float* srow, float4 a, float4 b) {
    asm volatile("red.global.add.v4.f32 [%0], {%1, %2, %3, %4};"
                 :: "l"(srow), "f"(a.x), "f"(a.y), "f"(a.z), "f"(a.w) : "memory");
    asm volatile("red.global.add.v4.f32 [%0], {%1, %2, %3, %4};"
                 :: "l"(srow + 4), "f"(b.x), "f"(b.y), "f"(b.z), "f"(b.w) : "memory");
}

// Pass 1: red-add exp(e) into g_sums[dst]. Warp-strided 2-edge batching.
// launch_bounds(256,8): 31 regs -> 8 blocks/SM -> ~100% occupancy; warp count
// (not per-thread MLP) is what covers the e-load latency here since REDs are
// fire-and-forget. dst loads DEFAULT policy (idx stays in L2 for pass 2).
__global__ __launch_bounds__(256, 8)
void scatter_sum_kernel(const float* __restrict__ e,
                        const int* __restrict__ dst,
                        int E) {
    int base = blockIdx.x * (blockDim.x * UNROLL) + threadIdx.x;

    int d[UNROLL];
    float4 va[UNROLL], vb[UNROLL];
#pragma unroll
    for (int k = 0; k < UNROLL; k++) {
        int i = base + k * blockDim.x;
        if (i < E) {
            d[k] = dst[i];
            ld256_evict_last(e + (size_t)i * HEADS, va[k], vb[k]);
        }
    }
#pragma unroll
    for (int k = 0; k < UNROLL; k++) {
        int i = base + k * blockDim.x;
        if (i < E) {
            float4 a = va[k], b = vb[k];
            exp8(a, b);
            red_row(g_sums + (size_t)d[k] * HEADS, a, b);
        }
    }
}

// Between passes: g_sums[i] = 1 / (g_sums[i] + eps), in place. 800K elements,
// fully L2-resident. Hoists the per-edge divide out of pass 2.
__global__ __launch_bounds__(256)
void recip_kernel(int n4) {
    int i = blockIdx.x * blockDim.x + threadIdx.x;
    if (i >= n4) return;
    const float eps = 1e-16f;
    float4 s = reinterpret_cast<const float4*>(g_sums)[i];
    s.x = __fdividef(1.0f, s.x + eps);
    s.y = __fdividef(1.0f, s.y + eps);
    s.z = __fdividef(1.0f, s.z + eps);
    s.w = __fdividef(1.0f, s.w + eps);
    reinterpret_cast<float4*>(g_sums)[i] = s;
}

// Pass 2: out = exp(e) * rcp[dst]. Pure multiply. Reverse block order so the
// earliest reads hit the L2-resident tail of e left by pass 1.
__global__ __launch_bounds__(256, 6)
void normalize_kernel(const float* __restrict__ e,
                      const int* __restrict__ dst,
                      float* __restrict__ out,
                      int E, int nBlocks) {
    int rb = nBlocks - 1 - blockIdx.x;
    int base = rb * ((int)blockDim.x * UNROLL) + threadIdx.x;

    int d[UNROLL];
#pragma unroll
    for (int k = 0; k < UNROLL; k++) {
        int i = base + k * blockDim.x;
        if (i < E) d[k] = dst[i];
    }

    float4 va[UNROLL], vb[UNROLL], sa[UNROLL], sb[UNROLL];
#pragma unroll
    for (int k = 0; k < UNROLL; k++) {
        int i = base + k * blockDim.x;
        if (i < E) {
            ld256(e + (size_t)i * HEADS, va[k], vb[k]);         // may hit pinned L2 lines
            ld256(g_sums + (size_t)d[k] * HEADS, sa[k], sb[k]); // L2 gather (reciprocals)
        }
    }

#pragma unroll
    for (int k = 0; k < UNROLL; k++) {
        int i = base + k * blockDim.x;
        if (i < E) {
            float4 a = va[k], b = vb[k];
            exp8(a, b);
            float4 s0 = sa[k], s1 = sb[k], o0, o1;
            o0.x = a.x * s0.x; o0.y = a.y * s0.y;
            o0.z = a.z * s0.z; o0.w = a.w * s0.w;
            o1.x = b.x * s1.x; o1.y = b.y * s1.y;
            o1.z = b.z * s1.z; o1.w = b.w * s1.w;
            st256_evict_first(out + (size_t)i * HEADS, o0, o1);
        }
    }
}

extern "C" void kernel_launch(void* const* d_in, const int* in_sizes, int n_in,
                              void* d_out, int out_size) {
    const float* e = (const float*)d_in[0];
    const int* edge_index = (const int*)d_in[1];
    int E = in_sizes[0] / HEADS;
    const int* dst = edge_index + (size_t)E;  // edge_index[1]
    float* out = (float*)d_out;

    // Zero g_sums via a memset graph node.
    void* sums_ptr = nullptr;
    cudaGetSymbolAddress(&sums_ptr, g_sums);
    cudaMemsetAsync(sums_ptr, 0, (size_t)N_NODES * HEADS * sizeof(float));

    const int T = 256;
    int perBlock = T * UNROLL;
    int nBlocks = (E + perBlock - 1) / perBlock;
    int n4 = N_NODES * HEADS / 4;

    scatter_sum_kernel<<<nBlocks, T>>>(e, dst, E);
    recip_kernel<<<(n4 + T - 1) / T, T>>>(n4);
    normalize_kernel<<<nBlocks, T>>>(e, dst, out, E, nBlocks);
}